// round 12
// baseline (speedup 1.0000x reference)
#include <cuda_runtime.h>
#include <cuda_bf16.h>
#include <cstdint>
#include <math.h>

#define NHEADS   16
#define NKV      4
#define HDIM     128
#define HIDDEN   2048
#define MAXSEQ   1024
#define EPSV     1e-6f
#define QSCALE   0.088388347648318447f   /* 1/sqrt(128) */
#define NSPLIT   8                       /* attention seq split */
#define KS       8                       /* GEMM k-split */
#define KCH      32                      /* k per staged chunk */
#define NCH      ((HIDDEN / KS) / KCH)   /* 8 chunks per block */

// GEMM smem layout (dynamic, 51200 B)
#define A_HL   2560
#define A_BUF  5120
#define B_OFF  10240
#define B_HL   10240
#define B_BUF  20480
#define SMEM_MMA 51200

// ---------------- scratch ---------------------------------------------------
__device__ __align__(16) float g_part[24 * KS * 32 * 128];
__device__ __align__(16) float g_attn[32 * HIDDEN];     // combined attn out (fp32)
__device__ __align__(16) float g_q[32 * NHEADS * HDIM];
__device__ __align__(16) float g_k[32 * NKV * HDIM];
__device__ __align__(16) float g_v[32 * NKV * HDIM];
__device__ __align__(16) float g_pa[32 * NKV * NSPLIT * 4 * HDIM];
__device__ float g_ps[32 * NKV * NSPLIT * 4];

// ---------------- wrappers ---------------------------------------------------
__device__ __forceinline__ uint32_t smem_u32(const void* p) {
    uint32_t a;
    asm("{ .reg .u64 t; cvta.to.shared.u64 t, %1; cvt.u32.u64 %0, t; }"
        : "=r"(a) : "l"(p));
    return a;
}
__device__ __forceinline__ void ldsm4(uint32_t& r0, uint32_t& r1,
                                      uint32_t& r2, uint32_t& r3, uint32_t a) {
    asm volatile("ldmatrix.sync.aligned.m8n8.x4.shared.b16 {%0,%1,%2,%3}, [%4];"
                 : "=r"(r0), "=r"(r1), "=r"(r2), "=r"(r3) : "r"(a));
}
__device__ __forceinline__ void mma16816(float* c,
                                         uint32_t a0, uint32_t a1, uint32_t a2,
                                         uint32_t a3, uint32_t b0, uint32_t b1) {
    asm volatile(
        "mma.sync.aligned.m16n8k16.row.col.f32.bf16.bf16.f32 "
        "{%0,%1,%2,%3}, {%4,%5,%6,%7}, {%8,%9}, {%0,%1,%2,%3};"
        : "+f"(c[0]), "+f"(c[1]), "+f"(c[2]), "+f"(c[3])
        : "r"(a0), "r"(a1), "r"(a2), "r"(a3), "r"(b0), "r"(b1));
}
__device__ __forceinline__ uint32_t bpack(__nv_bfloat16 a, __nv_bfloat16 b) {
    __nv_bfloat162 t = __halves2bfloat162(a, b);
    return *(uint32_t*)&t;
}

// 4-head packed butterfly: lane l ends with the full 128-dim dot for head l&3.
__device__ __forceinline__ float reduce4(float v0, float v1, float v2, float v3,
                                         int lane)
{
    const bool b0 = lane & 1, b1 = lane & 2;
    float x = b0 ? v1 : v0;
    float y = b0 ? v0 : v1;
    x += __shfl_xor_sync(0xffffffffu, y, 1);
    float z = b0 ? v3 : v2;
    float u = b0 ? v2 : v3;
    z += __shfl_xor_sync(0xffffffffu, u, 1);
    float p = b1 ? z : x;
    float q = b1 ? x : z;
    p += __shfl_xor_sync(0xffffffffu, q, 2);
    p += __shfl_xor_sync(0xffffffffu, p, 4);
    p += __shfl_xor_sync(0xffffffffu, p, 8);
    p += __shfl_xor_sync(0xffffffffu, p, 16);
    return p;
}

// ---------------- GEMM staging (A fp32, converted in-kernel) ----------------
struct WRegs {
    float4 v[4];
    float4 a;
};

__device__ __forceinline__ void ldg_chunk(WRegs& r,
    const float* __restrict__ A, const float* __restrict__ W, int k0)
{
    const int tid  = threadIdx.x;
    const int arow = tid >> 3, akq = (tid & 7) * 4;
    r.a = *(const float4*)(A + (size_t)arow * HIDDEN + k0 + akq);
    const int brow = tid >> 1, bk = (tid & 1) * 16;
#pragma unroll
    for (int j = 0; j < 4; j++)
        r.v[j] = *(const float4*)(W + (size_t)brow * HIDDEN + k0 + bk + j * 4);
}

__device__ __forceinline__ void sts_chunk(uint8_t* smem, int buf, const WRegs& r)
{
    const int tid  = threadIdx.x;
    const int arow = tid >> 3, akq = (tid & 7) * 4;
    uint8_t* A = smem + buf * A_BUF;
    {
        const __nv_bfloat16 h0 = __float2bfloat16(r.a.x);
        const __nv_bfloat16 h1 = __float2bfloat16(r.a.y);
        const __nv_bfloat16 h2 = __float2bfloat16(r.a.z);
        const __nv_bfloat16 h3 = __float2bfloat16(r.a.w);
        *(uint2*)(A + arow * 80 + akq * 2) =
            make_uint2(bpack(h0, h1), bpack(h2, h3));
        *(uint2*)(A + A_HL + arow * 80 + akq * 2) =
            make_uint2(bpack(__float2bfloat16(r.a.x - __bfloat162float(h0)),
                             __float2bfloat16(r.a.y - __bfloat162float(h1))),
                       bpack(__float2bfloat16(r.a.z - __bfloat162float(h2)),
                             __float2bfloat16(r.a.w - __bfloat162float(h3))));
    }

    const int brow = tid >> 1, bk = (tid & 1) * 16;
    uint8_t* Bh = smem + B_OFF + buf * B_BUF;
    uint8_t* Bl = Bh + B_HL;
    uint32_t h[8], l[8];
#pragma unroll
    for (int j = 0; j < 4; j++) {
        const float4 v = r.v[j];
        const __nv_bfloat16 h0 = __float2bfloat16(v.x);
        const __nv_bfloat16 h1 = __float2bfloat16(v.y);
        const __nv_bfloat16 h2 = __float2bfloat16(v.z);
        const __nv_bfloat16 h3 = __float2bfloat16(v.w);
        h[j * 2 + 0] = bpack(h0, h1);
        h[j * 2 + 1] = bpack(h2, h3);
        l[j * 2 + 0] = bpack(__float2bfloat16(v.x - __bfloat162float(h0)),
                             __float2bfloat16(v.y - __bfloat162float(h1)));
        l[j * 2 + 1] = bpack(__float2bfloat16(v.z - __bfloat162float(h2)),
                             __float2bfloat16(v.w - __bfloat162float(h3)));
    }
    *(uint4*)(Bh + brow * 80 + bk * 2)      = make_uint4(h[0], h[1], h[2], h[3]);
    *(uint4*)(Bh + brow * 80 + bk * 2 + 16) = make_uint4(h[4], h[5], h[6], h[7]);
    *(uint4*)(Bl + brow * 80 + bk * 2)      = make_uint4(l[0], l[1], l[2], l[3]);
    *(uint4*)(Bl + brow * 80 + bk * 2 + 16) = make_uint4(l[4], l[5], l[6], l[7]);
}

__device__ __forceinline__ void gemm_mma_body(
    const float* __restrict__ A, const float* __restrict__ W,
    float* __restrict__ outp, int k0)
{
    extern __shared__ uint8_t smem[];
    const uint32_t sb = smem_u32(smem);
    const int tid = threadIdx.x, warp = tid >> 5, lane = tid & 31;
    const int j = lane >> 3, r8 = lane & 7;

    float acc[2][2][4];
#pragma unroll
    for (int a = 0; a < 2; a++)
#pragma unroll
        for (int b = 0; b < 2; b++)
#pragma unroll
            for (int q = 0; q < 4; q++) acc[a][b][q] = 0.f;

    WRegs r;
    ldg_chunk(r, A, W, k0);
    sts_chunk(smem, 0, r);
    __syncthreads();

#pragma unroll 1
    for (int c = 0; c < NCH; c++) {
        if (c + 1 < NCH) ldg_chunk(r, A, W, k0 + (c + 1) * KCH);

        const uint32_t Ab = sb + (c & 1) * A_BUF;
        const uint32_t Bb = sb + B_OFF + (c & 1) * B_BUF;
#pragma unroll
        for (int ks = 0; ks < 2; ks++) {
            const uint32_t aaddr = Ab
                + (uint32_t)(((j & 1) * 8 + r8) * 80 + (ks * 2 + (j >> 1)) * 16);
            const uint32_t baddr = Bb
                + (uint32_t)((warp * 16 + (j >> 1) * 8 + r8) * 80
                             + (ks * 2 + (j & 1)) * 16);
            uint32_t f0, f1, f2, f3, g0, g1, g2, g3;
            uint32_t p0, p1, p2, p3, q0, q1, q2, q3;
            uint32_t bh0, bh1, bh2, bh3, bl0, bl1, bl2, bl3;
            ldsm4(f0, f1, f2, f3, aaddr);
            ldsm4(g0, g1, g2, g3, aaddr + 16 * 80);
            ldsm4(p0, p1, p2, p3, aaddr + A_HL);
            ldsm4(q0, q1, q2, q3, aaddr + A_HL + 16 * 80);
            ldsm4(bh0, bh1, bh2, bh3, baddr);
            ldsm4(bl0, bl1, bl2, bl3, baddr + B_HL);

            mma16816(acc[0][0], f0, f1, f2, f3, bh0, bh1);
            mma16816(acc[0][1], f0, f1, f2, f3, bh2, bh3);
            mma16816(acc[1][0], g0, g1, g2, g3, bh0, bh1);
            mma16816(acc[1][1], g0, g1, g2, g3, bh2, bh3);
            mma16816(acc[0][0], f0, f1, f2, f3, bl0, bl1);
            mma16816(acc[0][1], f0, f1, f2, f3, bl2, bl3);
            mma16816(acc[1][0], g0, g1, g2, g3, bl0, bl1);
            mma16816(acc[1][1], g0, g1, g2, g3, bl2, bl3);
            mma16816(acc[0][0], p0, p1, p2, p3, bh0, bh1);
            mma16816(acc[0][1], p0, p1, p2, p3, bh2, bh3);
            mma16816(acc[1][0], q0, q1, q2, q3, bh0, bh1);
            mma16816(acc[1][1], q0, q1, q2, q3, bh2, bh3);
        }
        if (c + 1 < NCH) sts_chunk(smem, (c + 1) & 1, r);
        __syncthreads();
    }

#pragma unroll
    for (int mt = 0; mt < 2; mt++)
#pragma unroll
        for (int nh = 0; nh < 2; nh++) {
            const float* cc = acc[mt][nh];
            const int m0 = mt * 16 + (lane >> 2);
            const int n  = warp * 16 + nh * 8 + (lane & 3) * 2;
            *(float2*)(outp + (size_t)m0 * 128 + n)       = make_float2(cc[0], cc[1]);
            *(float2*)(outp + (size_t)(m0 + 8) * 128 + n) = make_float2(cc[2], cc[3]);
        }
}

__global__ __launch_bounds__(256, 2) void gemm_qkv_mma(
    const float* __restrict__ x,
    const float* __restrict__ wq, const float* __restrict__ wk,
    const float* __restrict__ wv)
{
    const int tile = blockIdx.x, slice = blockIdx.y;
    const float* W;
    if (tile < 16)      W = wq + (size_t)tile * 128 * HIDDEN;
    else if (tile < 20) W = wk + (size_t)(tile - 16) * 128 * HIDDEN;
    else                W = wv + (size_t)(tile - 20) * 128 * HIDDEN;
    gemm_mma_body(x, W,
                  g_part + (size_t)(tile * KS + slice) * 4096,
                  slice * (HIDDEN / KS));
}

__global__ __launch_bounds__(256, 2) void gemm_o_mma(const float* __restrict__ wo)
{
    const int tile = blockIdx.x, slice = blockIdx.y;
    gemm_mma_body(g_attn, wo + (size_t)tile * 128 * HIDDEN,
                  g_part + (size_t)(tile * KS + slice) * 4096,
                  slice * (HIDDEN / KS));
}

// ---------------------------------------------------------------------------
// Reduce QKV partials + RMSnorm + RoPE, warp-per-head, float4, no barriers.
// grid (6, 32) x 128: head = blockIdx.x*4 + warp (0..23), lane owns 4 dims.
// ---------------------------------------------------------------------------
__global__ __launch_bounds__(128) void reduce_norm_rope(
    const float* __restrict__ position,
    const float* __restrict__ qnw, const float* __restrict__ knw)
{
    const int warp = threadIdx.x >> 5, lane = threadIdx.x & 31;
    const int head = blockIdx.x * 4 + warp, b = blockIdx.y;
    const int d4 = lane * 4;

    const float* base = g_part + (size_t)head * KS * 4096 + (size_t)b * 128 + d4;
    float4 v = make_float4(0.f, 0.f, 0.f, 0.f);
#pragma unroll
    for (int s = 0; s < KS; s++) {
        const float4 p = *(const float4*)(base + (size_t)s * 4096);
        v.x += p.x; v.y += p.y; v.z += p.z; v.w += p.w;
    }

    if (head >= 20) {                       // v head: plain store
        *(float4*)(g_v + (size_t)(b * NKV + head - 20) * HDIM + d4) = v;
        return;
    }

    // rmsnorm (warp reduction over sum of squares)
    float sq = v.x * v.x + v.y * v.y + v.z * v.z + v.w * v.w;
#pragma unroll
    for (int off = 16; off; off >>= 1)
        sq += __shfl_xor_sync(0xffffffffu, sq, off);
    const float norm = rsqrtf(sq * (1.f / 128.f) + EPSV);

    const float4 wv4 = (head < 16) ? *(const float4*)(qnw + d4)
                                   : *(const float4*)(knw + d4);
    float nv[4] = { v.x * norm * wv4.x, v.y * norm * wv4.y,
                    v.z * norm * wv4.z, v.w * norm * wv4.w };

    // rope: partner dims are at lane^16 (d<64 <=> lane<16)
    float other[4];
#pragma unroll
    for (int i = 0; i < 4; i++)
        other[i] = __shfl_xor_sync(0xffffffffu, nv[i], 16);

    const float pos = position[0];
    const bool first = lane < 16;
    float4 outv;
    float* po = &outv.x;
#pragma unroll
    for (int i = 0; i < 4; i++) {
        const int j = (d4 + i) & 63;
        const float fr = pos * exp2f((float)j * (-19.93156856932417f / 64.f));
        float cc, ss;
        sincosf(fr, &ss, &cc);
        po[i] = first ? (nv[i] * cc - other[i] * ss)
                      : (nv[i] * cc + other[i] * ss);
    }
    if (head < 16) {
        outv.x *= QSCALE; outv.y *= QSCALE; outv.z *= QSCALE; outv.w *= QSCALE;
        *(float4*)(g_q + (size_t)(b * NHEADS + head) * HDIM + d4) = outv;
    } else {
        *(float4*)(g_k + (size_t)(b * NKV + head - 16) * HDIM + d4) = outv;
    }
}

// ---------------------------------------------------------------------------
// Attention partial (R11, unchanged): single pass, no max subtraction
// (Cauchy-Schwarz bound keeps exp() fp32-safe), 2-deep register pipeline.
// Block (kv, b, split c) x 128 threads.
// ---------------------------------------------------------------------------
__global__ __launch_bounds__(128) void attn_part(
    const float* __restrict__ k_cache, const float* __restrict__ v_cache,
    const float* __restrict__ position)
{
    const int kv = blockIdx.x, b = blockIdx.y, c = blockIdx.z;
    const int tid = threadIdx.x;
    const int lane = tid & 31, w = tid >> 5;
    const int myh = lane & 3;
    const int pos = (int)position[0];
    const int S   = pos + 1;
    const int LEN = (S + NSPLIT - 1) / NSPLIT;
    const int lo  = c * LEN;
    const int hi  = min(S, lo + LEN);
    const int hic = min(hi, pos);
    const bool has_new = (pos >= lo) && (pos < hi);

    __shared__ float q_s[4][HDIM];
    __shared__ float wred[4][4];
    __shared__ float wout[4][4][HDIM];

    for (int i = tid; i < 4 * HDIM; i += 128) {
        const int h = i >> 7, d = i & 127;
        q_s[h][d] = g_q[(b * NHEADS + kv * 4 + h) * HDIM + d];
    }
    __syncthreads();

    float qr[4][4];
#pragma unroll
    for (int h = 0; h < 4; h++)
#pragma unroll
        for (int jj = 0; jj < 4; jj++) qr[h][jj] = q_s[h][lane * 4 + jj];

    const float* kbase = k_cache + (size_t)(b * NKV + kv) * MAXSEQ * HDIM + lane * 4;
    const float* vbase = v_cache + (size_t)(b * NKV + kv) * MAXSEQ * HDIM + lane * 4;

    float acc[4][4];
#pragma unroll
    for (int j = 0; j < 4; j++)
#pragma unroll
        for (int q = 0; q < 4; q++) acc[j][q] = 0.f;
    float lsum = 0.f;

    if (has_new && w == 0) {
        const float* knew = g_k + (b * NKV + kv) * HDIM;
        const float* vnew = g_v + (b * NKV + kv) * HDIM;
        const float4 rk = *(const float4*)(knew + lane * 4);
        const float4 rv = *(const float4*)(vnew + lane * 4);
        const float v0 = fmaf(rk.x, qr[0][0], fmaf(rk.y, qr[0][1],
                         fmaf(rk.z, qr[0][2], rk.w * qr[0][3])));
        const float v1 = fmaf(rk.x, qr[1][0], fmaf(rk.y, qr[1][1],
                         fmaf(rk.z, qr[1][2], rk.w * qr[1][3])));
        const float v2 = fmaf(rk.x, qr[2][0], fmaf(rk.y, qr[2][1],
                         fmaf(rk.z, qr[2][2], rk.w * qr[2][3])));
        const float v3 = fmaf(rk.x, qr[3][0], fmaf(rk.y, qr[3][1],
                         fmaf(rk.z, qr[3][2], rk.w * qr[3][3])));
        const float p = reduce4(v0, v1, v2, v3, lane);
        const float e = __expf(p);
        lsum += e;
        const float e1 = __shfl_xor_sync(0xffffffffu, e, 1);
        const float e2 = __shfl_xor_sync(0xffffffffu, e, 2);
        const float e3 = __shfl_xor_sync(0xffffffffu, e, 3);
        acc[0][0] = fmaf(e,  rv.x, acc[0][0]);
        acc[0][1] = fmaf(e,  rv.y, acc[0][1]);
        acc[0][2] = fmaf(e,  rv.z, acc[0][2]);
        acc[0][3] = fmaf(e,  rv.w, acc[0][3]);
        acc[1][0] = fmaf(e1, rv.x, acc[1][0]);
        acc[1][1] = fmaf(e1, rv.y, acc[1][1]);
        acc[1][2] = fmaf(e1, rv.z, acc[1][2]);
        acc[1][3] = fmaf(e1, rv.w, acc[1][3]);
        acc[2][0] = fmaf(e2, rv.x, acc[2][0]);
        acc[2][1] = fmaf(e2, rv.y, acc[2][1]);
        acc[2][2] = fmaf(e2, rv.z, acc[2][2]);
        acc[2][3] = fmaf(e2, rv.w, acc[2][3]);
        acc[3][0] = fmaf(e3, rv.x, acc[3][0]);
        acc[3][1] = fmaf(e3, rv.y, acc[3][1]);
        acc[3][2] = fmaf(e3, rv.z, acc[3][2]);
        acc[3][3] = fmaf(e3, rv.w, acc[3][3]);
    }

#define LOADG(dk, dv, s)                                                       \
    _Pragma("unroll")                                                          \
    for (int u_ = 0; u_ < 4; u_++) {                                           \
        const int ss_ = (s) + u_;                                              \
        if (ss_ < hic) {                                                       \
            dk[u_] = *(const float4*)(kbase + (size_t)ss_ * HDIM);             \
            dv[u_] = *(const float4*)(vbase + (size_t)ss_ * HDIM);             \
        }                                                                      \
    }

    int s0 = lo + w * 4;
    float4 rk[4], rv[4];
    if (s0 < hic) LOADG(rk, rv, s0);
#pragma unroll 1
    for (; s0 < hic; s0 += 16) {
        float4 nk[4], nv[4];
        const int s1 = s0 + 16;
        if (s1 < hic) LOADG(nk, nv, s1);
#pragma unroll
        for (int u = 0; u < 4; u++) {
            if (s0 + u < hic) {
                const float v0 = fmaf(rk[u].x, qr[0][0], fmaf(rk[u].y, qr[0][1],
                                 fmaf(rk[u].z, qr[0][2], rk[u].w * qr[0][3])));
                const float v1 = fmaf(rk[u].x, qr[1][0], fmaf(rk[u].y, qr[1][1],
                                 fmaf(rk[u].z, qr[1][2], rk[u].w * qr[1][3])));
                const float v2 = fmaf(rk[u].x, qr[2][0], fmaf(rk[u].y, qr[2][1],
                                 fmaf(rk[u].z, qr[2][2], rk[u].w * qr[2][3])));
                const float v3 = fmaf(rk[u].x, qr[3][0], fmaf(rk[u].y, qr[3][1],
                                 fmaf(rk[u].z, qr[3][2], rk[u].w * qr[3][3])));
                const float p = reduce4(v0, v1, v2, v3, lane);
                const float e = __expf(p);
                lsum += e;
                const float e1 = __shfl_xor_sync(0xffffffffu, e, 1);
                const float e2 = __shfl_xor_sync(0xffffffffu, e, 2);
                const float e3 = __shfl_xor_sync(0xffffffffu, e, 3);
                acc[0][0] = fmaf(e,  rv[u].x, acc[0][0]);
                acc[0][1] = fmaf(e,  rv[u].y, acc[0][1]);
                acc[0][2] = fmaf(e,  rv[u].z, acc[0][2]);
                acc[0][3] = fmaf(e,  rv[u].w, acc[0][3]);
                acc[1][0] = fmaf(e1, rv[u].x, acc[1][0]);
                acc[1][1] = fmaf(e1, rv[u].y, acc[1][1]);
                acc[1][2] = fmaf(e1, rv[u].z, acc[1][2]);
                acc[1][3] = fmaf(e1, rv[u].w, acc[1][3]);
                acc[2][0] = fmaf(e2, rv[u].x, acc[2][0]);
                acc[2][1] = fmaf(e2, rv[u].y, acc[2][1]);
                acc[2][2] = fmaf(e2, rv[u].z, acc[2][2]);
                acc[2][3] = fmaf(e2, rv[u].w, acc[2][3]);
                acc[3][0] = fmaf(e3, rv[u].x, acc[3][0]);
                acc[3][1] = fmaf(e3, rv[u].y, acc[3][1]);
                acc[3][2] = fmaf(e3, rv[u].z, acc[3][2]);
                acc[3][3] = fmaf(e3, rv[u].w, acc[3][3]);
            }
        }
#pragma unroll
        for (int u = 0; u < 4; u++) { rk[u] = nk[u]; rv[u] = nv[u]; }
    }
#undef LOADG

    if (lane < 4) wred[w][lane] = lsum;
#pragma unroll
    for (int j = 0; j < 4; j++) {
        float* wo_ = &wout[w][myh ^ j][lane * 4];
        wo_[0] = acc[j][0];
        wo_[1] = acc[j][1];
        wo_[2] = acc[j][2];
        wo_[3] = acc[j][3];
    }
    __syncthreads();

    if (tid < 4) {
        float v = wred[0][tid] + wred[1][tid] + wred[2][tid] + wred[3][tid];
        g_ps[((b * NKV + kv) * NSPLIT + c) * 4 + tid] = v;
    }

    for (int i = tid; i < 4 * HDIM; i += 128) {
        const int h = i >> 7, d = i & 127;
        const float v = wout[0][h][d] + wout[1][h][d]
                      + wout[2][h][d] + wout[3][h][d];
        g_pa[(((size_t)(b * NKV + kv) * NSPLIT + c) * 4 + h) * HDIM + d] = v;
    }
}

// ---------------------------------------------------------------------------
// Combine flash partials (common scale) -> fp32 g_attn. Warp-per-head,
// float4 loads. grid (4, 32) x 128.
// ---------------------------------------------------------------------------
__global__ __launch_bounds__(128) void combine_conv()
{
    const int warp = threadIdx.x >> 5, lane = threadIdx.x & 31;
    const int hidx = blockIdx.x * 4 + warp, b = blockIdx.y;
    const int kv = hidx >> 2, h = hidx & 3;
    const int pb = ((b * NKV + kv) * NSPLIT) * 4 + h;
    const int d4 = lane * 4;

    float den = 0.f;
#pragma unroll
    for (int c = 0; c < NSPLIT; c++) den += g_ps[pb + c * 4];
    const float inv = 1.f / den;

    float4 val = make_float4(0.f, 0.f, 0.f, 0.f);
#pragma unroll
    for (int c = 0; c < NSPLIT; c++) {
        const float4 v = *(const float4*)&g_pa[(size_t)(pb + c * 4) * HDIM + d4];
        val.x += v.x; val.y += v.y; val.z += v.z; val.w += v.w;
    }
    val.x *= inv; val.y *= inv; val.z *= inv; val.w *= inv;
    *(float4*)(g_attn + (size_t)b * HIDDEN + hidx * 128 + d4) = val;
}

// Final reduce for O projection. Warp-per-tile-quarter, float4.
// grid (4, 32) x 128.
__global__ __launch_bounds__(128) void reduce_out(float* __restrict__ out)
{
    const int warp = threadIdx.x >> 5, lane = threadIdx.x & 31;
    const int tile = blockIdx.x * 4 + warp, b = blockIdx.y;
    const int d4 = lane * 4;

    const float* base = g_part + (size_t)tile * KS * 4096 + (size_t)b * 128 + d4;
    float4 v = make_float4(0.f, 0.f, 0.f, 0.f);
#pragma unroll
    for (int s = 0; s < KS; s++) {
        const float4 p = *(const float4*)(base + (size_t)s * 4096);
        v.x += p.x; v.y += p.y; v.z += p.z; v.w += p.w;
    }
    *(float4*)(out + (size_t)b * HIDDEN + tile * 128 + d4) = v;
}

// ---------------------------------------------------------------------------
extern "C" void kernel_launch(void* const* d_in, const int* in_sizes, int n_in,
                              void* d_out, int out_size)
{
    const float* x        = (const float*)d_in[0];
    const float* position = (const float*)d_in[1];
    const float* k_cache  = (const float*)d_in[3];
    const float* v_cache  = (const float*)d_in[4];
    const float* wq       = (const float*)d_in[6];
    const float* wk       = (const float*)d_in[7];
    const float* wv       = (const float*)d_in[8];
    const float* wo       = (const float*)d_in[9];
    const float* qnw      = (const float*)d_in[10];
    const float* knw      = (const float*)d_in[11];
    float* out            = (float*)d_out;

    cudaFuncSetAttribute(gemm_qkv_mma, cudaFuncAttributeMaxDynamicSharedMemorySize, SMEM_MMA);
    cudaFuncSetAttribute(gemm_o_mma,   cudaFuncAttributeMaxDynamicSharedMemorySize, SMEM_MMA);

    gemm_qkv_mma<<<dim3(24, KS), 256, SMEM_MMA>>>(x, wq, wk, wv);
    reduce_norm_rope<<<dim3(6, 32), 128>>>(position, qnw, knw);
    attn_part<<<dim3(NKV, 32, NSPLIT), 128>>>(k_cache, v_cache, position);
    combine_conv<<<dim3(4, 32), 128>>>();
    gemm_o_mma<<<dim3(16, KS), 256, SMEM_MMA>>>(wo);
    reduce_out<<<dim3(4, 32), 128>>>(out);
}

// round 13
// speedup vs baseline: 1.0375x; 1.0375x over previous
#include <cuda_runtime.h>
#include <cuda_bf16.h>
#include <cstdint>
#include <math.h>

#define NHEADS   16
#define NKV      4
#define HDIM     128
#define HIDDEN   2048
#define MAXSEQ   1024
#define EPSV     1e-6f
#define QSCALE   0.088388347648318447f   /* 1/sqrt(128) */
#define NSPLIT   8                       /* attention seq split */
#define KS       8                       /* GEMM k-split */
#define KCH      32                      /* k per staged chunk */
#define NCH      ((HIDDEN / KS) / KCH)   /* 8 chunks per block */

// GEMM smem layout (dynamic, 51200 B)
#define A_HL   2560
#define A_BUF  5120
#define B_OFF  10240
#define B_HL   10240
#define B_BUF  20480
#define SMEM_MMA 51200

// ---------------- scratch ---------------------------------------------------
__device__ __align__(16) float g_part[24 * KS * 32 * 128];
__device__ __align__(16) float g_attn[32 * HIDDEN];     // combined attn out (fp32)
__device__ __align__(16) float g_q[32 * NHEADS * HDIM];
__device__ __align__(16) float g_k[32 * NKV * HDIM];
__device__ __align__(16) float g_v[32 * NKV * HDIM];
__device__ __align__(16) float g_pa[32 * NKV * NSPLIT * 4 * HDIM];
__device__ float g_ps[32 * NKV * NSPLIT * 4];

// ---------------- wrappers ---------------------------------------------------
__device__ __forceinline__ uint32_t smem_u32(const void* p) {
    uint32_t a;
    asm("{ .reg .u64 t; cvta.to.shared.u64 t, %1; cvt.u32.u64 %0, t; }"
        : "=r"(a) : "l"(p));
    return a;
}
__device__ __forceinline__ void ldsm4(uint32_t& r0, uint32_t& r1,
                                      uint32_t& r2, uint32_t& r3, uint32_t a) {
    asm volatile("ldmatrix.sync.aligned.m8n8.x4.shared.b16 {%0,%1,%2,%3}, [%4];"
                 : "=r"(r0), "=r"(r1), "=r"(r2), "=r"(r3) : "r"(a));
}
__device__ __forceinline__ void mma16816(float* c,
                                         uint32_t a0, uint32_t a1, uint32_t a2,
                                         uint32_t a3, uint32_t b0, uint32_t b1) {
    asm volatile(
        "mma.sync.aligned.m16n8k16.row.col.f32.bf16.bf16.f32 "
        "{%0,%1,%2,%3}, {%4,%5,%6,%7}, {%8,%9}, {%0,%1,%2,%3};"
        : "+f"(c[0]), "+f"(c[1]), "+f"(c[2]), "+f"(c[3])
        : "r"(a0), "r"(a1), "r"(a2), "r"(a3), "r"(b0), "r"(b1));
}
__device__ __forceinline__ uint32_t bpack(__nv_bfloat16 a, __nv_bfloat16 b) {
    __nv_bfloat162 t = __halves2bfloat162(a, b);
    return *(uint32_t*)&t;
}

// 4-head packed butterfly: lane l ends with the full 128-dim dot for head l&3.
__device__ __forceinline__ float reduce4(float v0, float v1, float v2, float v3,
                                         int lane)
{
    const bool b0 = lane & 1, b1 = lane & 2;
    float x = b0 ? v1 : v0;
    float y = b0 ? v0 : v1;
    x += __shfl_xor_sync(0xffffffffu, y, 1);
    float z = b0 ? v3 : v2;
    float u = b0 ? v2 : v3;
    z += __shfl_xor_sync(0xffffffffu, u, 1);
    float p = b1 ? z : x;
    float q = b1 ? x : z;
    p += __shfl_xor_sync(0xffffffffu, q, 2);
    p += __shfl_xor_sync(0xffffffffu, p, 4);
    p += __shfl_xor_sync(0xffffffffu, p, 8);
    p += __shfl_xor_sync(0xffffffffu, p, 16);
    return p;
}

// ---------------- GEMM staging (A fp32, converted in-kernel) ----------------
struct WRegs {
    float4 v[4];
    float4 a;
};

__device__ __forceinline__ void ldg_chunk(WRegs& r,
    const float* __restrict__ A, const float* __restrict__ W, int k0)
{
    const int tid  = threadIdx.x;
    const int arow = tid >> 3, akq = (tid & 7) * 4;
    r.a = *(const float4*)(A + (size_t)arow * HIDDEN + k0 + akq);
    const int brow = tid >> 1, bk = (tid & 1) * 16;
#pragma unroll
    for (int j = 0; j < 4; j++)
        r.v[j] = *(const float4*)(W + (size_t)brow * HIDDEN + k0 + bk + j * 4);
}

__device__ __forceinline__ void sts_chunk(uint8_t* smem, int buf, const WRegs& r)
{
    const int tid  = threadIdx.x;
    const int arow = tid >> 3, akq = (tid & 7) * 4;
    uint8_t* A = smem + buf * A_BUF;
    {
        const __nv_bfloat16 h0 = __float2bfloat16(r.a.x);
        const __nv_bfloat16 h1 = __float2bfloat16(r.a.y);
        const __nv_bfloat16 h2 = __float2bfloat16(r.a.z);
        const __nv_bfloat16 h3 = __float2bfloat16(r.a.w);
        *(uint2*)(A + arow * 80 + akq * 2) =
            make_uint2(bpack(h0, h1), bpack(h2, h3));
        *(uint2*)(A + A_HL + arow * 80 + akq * 2) =
            make_uint2(bpack(__float2bfloat16(r.a.x - __bfloat162float(h0)),
                             __float2bfloat16(r.a.y - __bfloat162float(h1))),
                       bpack(__float2bfloat16(r.a.z - __bfloat162float(h2)),
                             __float2bfloat16(r.a.w - __bfloat162float(h3))));
    }

    const int brow = tid >> 1, bk = (tid & 1) * 16;
    uint8_t* Bh = smem + B_OFF + buf * B_BUF;
    uint8_t* Bl = Bh + B_HL;
    uint32_t h[8], l[8];
#pragma unroll
    for (int j = 0; j < 4; j++) {
        const float4 v = r.v[j];
        const __nv_bfloat16 h0 = __float2bfloat16(v.x);
        const __nv_bfloat16 h1 = __float2bfloat16(v.y);
        const __nv_bfloat16 h2 = __float2bfloat16(v.z);
        const __nv_bfloat16 h3 = __float2bfloat16(v.w);
        h[j * 2 + 0] = bpack(h0, h1);
        h[j * 2 + 1] = bpack(h2, h3);
        l[j * 2 + 0] = bpack(__float2bfloat16(v.x - __bfloat162float(h0)),
                             __float2bfloat16(v.y - __bfloat162float(h1)));
        l[j * 2 + 1] = bpack(__float2bfloat16(v.z - __bfloat162float(h2)),
                             __float2bfloat16(v.w - __bfloat162float(h3)));
    }
    *(uint4*)(Bh + brow * 80 + bk * 2)      = make_uint4(h[0], h[1], h[2], h[3]);
    *(uint4*)(Bh + brow * 80 + bk * 2 + 16) = make_uint4(h[4], h[5], h[6], h[7]);
    *(uint4*)(Bl + brow * 80 + bk * 2)      = make_uint4(l[0], l[1], l[2], l[3]);
    *(uint4*)(Bl + brow * 80 + bk * 2 + 16) = make_uint4(l[4], l[5], l[6], l[7]);
}

__device__ __forceinline__ void gemm_mma_body(
    const float* __restrict__ A, const float* __restrict__ W,
    float* __restrict__ outp, int k0)
{
    extern __shared__ uint8_t smem[];
    const uint32_t sb = smem_u32(smem);
    const int tid = threadIdx.x, warp = tid >> 5, lane = tid & 31;
    const int j = lane >> 3, r8 = lane & 7;

    float acc[2][2][4];
#pragma unroll
    for (int a = 0; a < 2; a++)
#pragma unroll
        for (int b = 0; b < 2; b++)
#pragma unroll
            for (int q = 0; q < 4; q++) acc[a][b][q] = 0.f;

    WRegs r;
    ldg_chunk(r, A, W, k0);
    sts_chunk(smem, 0, r);
    __syncthreads();

#pragma unroll 1
    for (int c = 0; c < NCH; c++) {
        if (c + 1 < NCH) ldg_chunk(r, A, W, k0 + (c + 1) * KCH);

        const uint32_t Ab = sb + (c & 1) * A_BUF;
        const uint32_t Bb = sb + B_OFF + (c & 1) * B_BUF;
#pragma unroll
        for (int ks = 0; ks < 2; ks++) {
            const uint32_t aaddr = Ab
                + (uint32_t)(((j & 1) * 8 + r8) * 80 + (ks * 2 + (j >> 1)) * 16);
            const uint32_t baddr = Bb
                + (uint32_t)((warp * 16 + (j >> 1) * 8 + r8) * 80
                             + (ks * 2 + (j & 1)) * 16);
            uint32_t f0, f1, f2, f3, g0, g1, g2, g3;
            uint32_t p0, p1, p2, p3, q0, q1, q2, q3;
            uint32_t bh0, bh1, bh2, bh3, bl0, bl1, bl2, bl3;
            ldsm4(f0, f1, f2, f3, aaddr);
            ldsm4(g0, g1, g2, g3, aaddr + 16 * 80);
            ldsm4(p0, p1, p2, p3, aaddr + A_HL);
            ldsm4(q0, q1, q2, q3, aaddr + A_HL + 16 * 80);
            ldsm4(bh0, bh1, bh2, bh3, baddr);
            ldsm4(bl0, bl1, bl2, bl3, baddr + B_HL);

            mma16816(acc[0][0], f0, f1, f2, f3, bh0, bh1);
            mma16816(acc[0][1], f0, f1, f2, f3, bh2, bh3);
            mma16816(acc[1][0], g0, g1, g2, g3, bh0, bh1);
            mma16816(acc[1][1], g0, g1, g2, g3, bh2, bh3);
            mma16816(acc[0][0], f0, f1, f2, f3, bl0, bl1);
            mma16816(acc[0][1], f0, f1, f2, f3, bl2, bl3);
            mma16816(acc[1][0], g0, g1, g2, g3, bl0, bl1);
            mma16816(acc[1][1], g0, g1, g2, g3, bl2, bl3);
            mma16816(acc[0][0], p0, p1, p2, p3, bh0, bh1);
            mma16816(acc[0][1], p0, p1, p2, p3, bh2, bh3);
            mma16816(acc[1][0], q0, q1, q2, q3, bh0, bh1);
            mma16816(acc[1][1], q0, q1, q2, q3, bh2, bh3);
        }
        if (c + 1 < NCH) sts_chunk(smem, (c + 1) & 1, r);
        __syncthreads();
    }

#pragma unroll
    for (int mt = 0; mt < 2; mt++)
#pragma unroll
        for (int nh = 0; nh < 2; nh++) {
            const float* cc = acc[mt][nh];
            const int m0 = mt * 16 + (lane >> 2);
            const int n  = warp * 16 + nh * 8 + (lane & 3) * 2;
            *(float2*)(outp + (size_t)m0 * 128 + n)       = make_float2(cc[0], cc[1]);
            *(float2*)(outp + (size_t)(m0 + 8) * 128 + n) = make_float2(cc[2], cc[3]);
        }
}

__global__ __launch_bounds__(256, 2) void gemm_qkv_mma(
    const float* __restrict__ x,
    const float* __restrict__ wq, const float* __restrict__ wk,
    const float* __restrict__ wv)
{
    const int tile = blockIdx.x, slice = blockIdx.y;
    const float* W;
    if (tile < 16)      W = wq + (size_t)tile * 128 * HIDDEN;
    else if (tile < 20) W = wk + (size_t)(tile - 16) * 128 * HIDDEN;
    else                W = wv + (size_t)(tile - 20) * 128 * HIDDEN;
    gemm_mma_body(x, W,
                  g_part + (size_t)(tile * KS + slice) * 4096,
                  slice * (HIDDEN / KS));
}

__global__ __launch_bounds__(256, 2) void gemm_o_mma(const float* __restrict__ wo)
{
    const int tile = blockIdx.x, slice = blockIdx.y;
    gemm_mma_body(g_attn, wo + (size_t)tile * 128 * HIDDEN,
                  g_part + (size_t)(tile * KS + slice) * 4096,
                  slice * (HIDDEN / KS));
}

// ---------------------------------------------------------------------------
// Reduce QKV partials + RMSnorm + RoPE (R11 version). grid (24, 32) x 128.
// ---------------------------------------------------------------------------
__global__ __launch_bounds__(128) void reduce_norm_rope(
    const float* __restrict__ position,
    const float* __restrict__ qnw, const float* __restrict__ knw)
{
    const int head = blockIdx.x, b = blockIdx.y, d = threadIdx.x;
    const size_t base = (size_t)head * KS * 4096 + (size_t)b * 128 + d;
    float v = 0.f;
#pragma unroll
    for (int s = 0; s < KS; s++) v += g_part[base + (size_t)s * 4096];

    if (head >= 20) {
        g_v[(b * NKV + head - 20) * HDIM + d] = v;
        return;
    }

    __shared__ float red[4];
    __shared__ float sv[128];

    float sq = v * v;
#pragma unroll
    for (int off = 16; off; off >>= 1)
        sq += __shfl_xor_sync(0xffffffffu, sq, off);
    if ((d & 31) == 0) red[d >> 5] = sq;
    __syncthreads();
    const float ssq  = red[0] + red[1] + red[2] + red[3];
    const float norm = rsqrtf(ssq * (1.f / 128.f) + EPSV);
    const float nv   = v * norm * ((head < 16) ? qnw[d] : knw[d]);
    sv[d] = nv;
    __syncthreads();

    const float pos = position[0];
    const int   jj  = d & 63;
    const float fr  = pos * exp2f((float)jj * (-19.93156856932417f / 64.f));
    float c, s;
    sincosf(fr, &s, &c);
    const float other = (d < 64) ? sv[d + 64] : sv[d - 64];
    const float out   = (d < 64) ? (nv * c - other * s)
                                 : (nv * c + other * s);
    if (head < 16) g_q[(b * NHEADS + head) * HDIM + d] = out * QSCALE;
    else           g_k[(b * NKV + head - 16) * HDIM + d] = out;
}

// ---------------------------------------------------------------------------
// Attention partial (R11, unchanged): single pass, no max subtraction
// (Cauchy-Schwarz bound keeps exp() fp32-safe), 2-deep register pipeline.
// Block (kv, b, split c) x 128 threads.
// ---------------------------------------------------------------------------
__global__ __launch_bounds__(128) void attn_part(
    const float* __restrict__ k_cache, const float* __restrict__ v_cache,
    const float* __restrict__ position)
{
    const int kv = blockIdx.x, b = blockIdx.y, c = blockIdx.z;
    const int tid = threadIdx.x;
    const int lane = tid & 31, w = tid >> 5;
    const int myh = lane & 3;
    const int pos = (int)position[0];
    const int S   = pos + 1;
    const int LEN = (S + NSPLIT - 1) / NSPLIT;
    const int lo  = c * LEN;
    const int hi  = min(S, lo + LEN);
    const int hic = min(hi, pos);
    const bool has_new = (pos >= lo) && (pos < hi);

    __shared__ float q_s[4][HDIM];
    __shared__ float wred[4][4];
    __shared__ float wout[4][4][HDIM];

    for (int i = tid; i < 4 * HDIM; i += 128) {
        const int h = i >> 7, d = i & 127;
        q_s[h][d] = g_q[(b * NHEADS + kv * 4 + h) * HDIM + d];
    }
    __syncthreads();

    float qr[4][4];
#pragma unroll
    for (int h = 0; h < 4; h++)
#pragma unroll
        for (int jj = 0; jj < 4; jj++) qr[h][jj] = q_s[h][lane * 4 + jj];

    const float* kbase = k_cache + (size_t)(b * NKV + kv) * MAXSEQ * HDIM + lane * 4;
    const float* vbase = v_cache + (size_t)(b * NKV + kv) * MAXSEQ * HDIM + lane * 4;

    float acc[4][4];
#pragma unroll
    for (int j = 0; j < 4; j++)
#pragma unroll
        for (int q = 0; q < 4; q++) acc[j][q] = 0.f;
    float lsum = 0.f;

    if (has_new && w == 0) {
        const float* knew = g_k + (b * NKV + kv) * HDIM;
        const float* vnew = g_v + (b * NKV + kv) * HDIM;
        const float4 rk = *(const float4*)(knew + lane * 4);
        const float4 rv = *(const float4*)(vnew + lane * 4);
        const float v0 = fmaf(rk.x, qr[0][0], fmaf(rk.y, qr[0][1],
                         fmaf(rk.z, qr[0][2], rk.w * qr[0][3])));
        const float v1 = fmaf(rk.x, qr[1][0], fmaf(rk.y, qr[1][1],
                         fmaf(rk.z, qr[1][2], rk.w * qr[1][3])));
        const float v2 = fmaf(rk.x, qr[2][0], fmaf(rk.y, qr[2][1],
                         fmaf(rk.z, qr[2][2], rk.w * qr[2][3])));
        const float v3 = fmaf(rk.x, qr[3][0], fmaf(rk.y, qr[3][1],
                         fmaf(rk.z, qr[3][2], rk.w * qr[3][3])));
        const float p = reduce4(v0, v1, v2, v3, lane);
        const float e = __expf(p);
        lsum += e;
        const float e1 = __shfl_xor_sync(0xffffffffu, e, 1);
        const float e2 = __shfl_xor_sync(0xffffffffu, e, 2);
        const float e3 = __shfl_xor_sync(0xffffffffu, e, 3);
        acc[0][0] = fmaf(e,  rv.x, acc[0][0]);
        acc[0][1] = fmaf(e,  rv.y, acc[0][1]);
        acc[0][2] = fmaf(e,  rv.z, acc[0][2]);
        acc[0][3] = fmaf(e,  rv.w, acc[0][3]);
        acc[1][0] = fmaf(e1, rv.x, acc[1][0]);
        acc[1][1] = fmaf(e1, rv.y, acc[1][1]);
        acc[1][2] = fmaf(e1, rv.z, acc[1][2]);
        acc[1][3] = fmaf(e1, rv.w, acc[1][3]);
        acc[2][0] = fmaf(e2, rv.x, acc[2][0]);
        acc[2][1] = fmaf(e2, rv.y, acc[2][1]);
        acc[2][2] = fmaf(e2, rv.z, acc[2][2]);
        acc[2][3] = fmaf(e2, rv.w, acc[2][3]);
        acc[3][0] = fmaf(e3, rv.x, acc[3][0]);
        acc[3][1] = fmaf(e3, rv.y, acc[3][1]);
        acc[3][2] = fmaf(e3, rv.z, acc[3][2]);
        acc[3][3] = fmaf(e3, rv.w, acc[3][3]);
    }

#define LOADG(dk, dv, s)                                                       \
    _Pragma("unroll")                                                          \
    for (int u_ = 0; u_ < 4; u_++) {                                           \
        const int ss_ = (s) + u_;                                              \
        if (ss_ < hic) {                                                       \
            dk[u_] = *(const float4*)(kbase + (size_t)ss_ * HDIM);             \
            dv[u_] = *(const float4*)(vbase + (size_t)ss_ * HDIM);             \
        }                                                                      \
    }

    int s0 = lo + w * 4;
    float4 rk[4], rv[4];
    if (s0 < hic) LOADG(rk, rv, s0);
#pragma unroll 1
    for (; s0 < hic; s0 += 16) {
        float4 nk[4], nv[4];
        const int s1 = s0 + 16;
        if (s1 < hic) LOADG(nk, nv, s1);
#pragma unroll
        for (int u = 0; u < 4; u++) {
            if (s0 + u < hic) {
                const float v0 = fmaf(rk[u].x, qr[0][0], fmaf(rk[u].y, qr[0][1],
                                 fmaf(rk[u].z, qr[0][2], rk[u].w * qr[0][3])));
                const float v1 = fmaf(rk[u].x, qr[1][0], fmaf(rk[u].y, qr[1][1],
                                 fmaf(rk[u].z, qr[1][2], rk[u].w * qr[1][3])));
                const float v2 = fmaf(rk[u].x, qr[2][0], fmaf(rk[u].y, qr[2][1],
                                 fmaf(rk[u].z, qr[2][2], rk[u].w * qr[2][3])));
                const float v3 = fmaf(rk[u].x, qr[3][0], fmaf(rk[u].y, qr[3][1],
                                 fmaf(rk[u].z, qr[3][2], rk[u].w * qr[3][3])));
                const float p = reduce4(v0, v1, v2, v3, lane);
                const float e = __expf(p);
                lsum += e;
                const float e1 = __shfl_xor_sync(0xffffffffu, e, 1);
                const float e2 = __shfl_xor_sync(0xffffffffu, e, 2);
                const float e3 = __shfl_xor_sync(0xffffffffu, e, 3);
                acc[0][0] = fmaf(e,  rv[u].x, acc[0][0]);
                acc[0][1] = fmaf(e,  rv[u].y, acc[0][1]);
                acc[0][2] = fmaf(e,  rv[u].z, acc[0][2]);
                acc[0][3] = fmaf(e,  rv[u].w, acc[0][3]);
                acc[1][0] = fmaf(e1, rv[u].x, acc[1][0]);
                acc[1][1] = fmaf(e1, rv[u].y, acc[1][1]);
                acc[1][2] = fmaf(e1, rv[u].z, acc[1][2]);
                acc[1][3] = fmaf(e1, rv[u].w, acc[1][3]);
                acc[2][0] = fmaf(e2, rv[u].x, acc[2][0]);
                acc[2][1] = fmaf(e2, rv[u].y, acc[2][1]);
                acc[2][2] = fmaf(e2, rv[u].z, acc[2][2]);
                acc[2][3] = fmaf(e2, rv[u].w, acc[2][3]);
                acc[3][0] = fmaf(e3, rv[u].x, acc[3][0]);
                acc[3][1] = fmaf(e3, rv[u].y, acc[3][1]);
                acc[3][2] = fmaf(e3, rv[u].z, acc[3][2]);
                acc[3][3] = fmaf(e3, rv[u].w, acc[3][3]);
            }
        }
#pragma unroll
        for (int u = 0; u < 4; u++) { rk[u] = nk[u]; rv[u] = nv[u]; }
    }
#undef LOADG

    if (lane < 4) wred[w][lane] = lsum;
#pragma unroll
    for (int j = 0; j < 4; j++) {
        float* wo_ = &wout[w][myh ^ j][lane * 4];
        wo_[0] = acc[j][0];
        wo_[1] = acc[j][1];
        wo_[2] = acc[j][2];
        wo_[3] = acc[j][3];
    }
    __syncthreads();

    if (tid < 4) {
        float v = wred[0][tid] + wred[1][tid] + wred[2][tid] + wred[3][tid];
        g_ps[((b * NKV + kv) * NSPLIT + c) * 4 + tid] = v;
    }

    for (int i = tid; i < 4 * HDIM; i += 128) {
        const int h = i >> 7, d = i & 127;
        const float v = wout[0][h][d] + wout[1][h][d]
                      + wout[2][h][d] + wout[3][h][d];
        g_pa[(((size_t)(b * NKV + kv) * NSPLIT + c) * 4 + h) * HDIM + d] = v;
    }
}

// ---------------------------------------------------------------------------
// Combine flash partials v3: high parallelism + vector loads.
// grid (16 heads, 32 b) x 256 threads: warp c loads split c (float4/lane),
// one barrier, then 128 threads do the 8-way sum + divide.
// ---------------------------------------------------------------------------
__global__ __launch_bounds__(256) void combine_conv()
{
    const int hidx = blockIdx.x, b = blockIdx.y;
    const int kv = hidx >> 2, h = hidx & 3;
    const int tid = threadIdx.x;
    const int w = tid >> 5, lane = tid & 31;

    __shared__ float part[NSPLIT][HDIM];
    __shared__ float sden[NSPLIT];

    const int pb = ((b * NKV + kv) * NSPLIT + w) * 4 + h;
    const float4 v = *(const float4*)&g_pa[(size_t)pb * HDIM + lane * 4];
    *(float4*)&part[w][lane * 4] = v;
    if (lane == 0) sden[w] = g_ps[pb];
    __syncthreads();

    if (tid < 128) {
        const float den = sden[0] + sden[1] + sden[2] + sden[3]
                        + sden[4] + sden[5] + sden[6] + sden[7];
        float val = 0.f;
#pragma unroll
        for (int c = 0; c < NSPLIT; c++) val += part[c][tid];
        g_attn[(size_t)b * HIDDEN + hidx * 128 + tid] = val / den;
    }
}

// Final reduce for O projection (R11 version). grid (16, 32) x 128.
__global__ __launch_bounds__(128) void reduce_out(float* __restrict__ out)
{
    const int tile = blockIdx.x, b = blockIdx.y, d = threadIdx.x;
    const size_t base = (size_t)tile * KS * 4096 + (size_t)b * 128 + d;
    float v = 0.f;
#pragma unroll
    for (int s = 0; s < KS; s++) v += g_part[base + (size_t)s * 4096];
    out[b * HIDDEN + tile * 128 + d] = v;
}

// ---------------------------------------------------------------------------
extern "C" void kernel_launch(void* const* d_in, const int* in_sizes, int n_in,
                              void* d_out, int out_size)
{
    const float* x        = (const float*)d_in[0];
    const float* position = (const float*)d_in[1];
    const float* k_cache  = (const float*)d_in[3];
    const float* v_cache  = (const float*)d_in[4];
    const float* wq       = (const float*)d_in[6];
    const float* wk       = (const float*)d_in[7];
    const float* wv       = (const float*)d_in[8];
    const float* wo       = (const float*)d_in[9];
    const float* qnw      = (const float*)d_in[10];
    const float* knw      = (const float*)d_in[11];
    float* out            = (float*)d_out;

    cudaFuncSetAttribute(gemm_qkv_mma, cudaFuncAttributeMaxDynamicSharedMemorySize, SMEM_MMA);
    cudaFuncSetAttribute(gemm_o_mma,   cudaFuncAttributeMaxDynamicSharedMemorySize, SMEM_MMA);

    gemm_qkv_mma<<<dim3(24, KS), 256, SMEM_MMA>>>(x, wq, wk, wv);
    reduce_norm_rope<<<dim3(24, 32), 128>>>(position, qnw, knw);
    attn_part<<<dim3(NKV, 32, NSPLIT), 128>>>(k_cache, v_cache, position);
    combine_conv<<<dim3(16, 32), 256>>>();
    gemm_o_mma<<<dim3(16, KS), 256, SMEM_MMA>>>(wo);
    reduce_out<<<dim3(16, 32), 128>>>(out);
}

// round 15
// speedup vs baseline: 1.1231x; 1.0825x over previous
#include <cuda_runtime.h>
#include <cuda_bf16.h>
#include <cstdint>
#include <math.h>

#define NHEADS   16
#define NKV      4
#define HDIM     128
#define HIDDEN   2048
#define MAXSEQ   1024
#define EPSV     1e-6f
#define QSCALE   0.088388347648318447f   /* 1/sqrt(128) */
#define NSPLIT   8                       /* attention seq split */
#define KS       8                       /* QKV GEMM k-split */
#define KSO      16                      /* O GEMM slices (1 head each) */
#define KCH      32                      /* k per staged chunk */

// GEMM smem layout (dynamic)
#define A_HL   2560
#define A_BUF  5120
#define B_OFF  10240
#define B_HL   10240
#define B_BUF  20480
#define SMEM_MMA 51200
#define SMEM_O  (SMEM_MMA + 32 * 128 * 4)   /* + combined-A tile = 67584 */

// ---------------- scratch ---------------------------------------------------
__device__ __align__(16) float g_part[256 * 4096];   // QKV: 24x8 tiles; O: 16x16
__device__ __align__(16) float g_pa[32 * NKV * NSPLIT * 4 * HDIM];
__device__ float g_ps[32 * NKV * NSPLIT * 4];

// ---------------- wrappers ---------------------------------------------------
__device__ __forceinline__ uint32_t smem_u32(const void* p) {
    uint32_t a;
    asm("{ .reg .u64 t; cvta.to.shared.u64 t, %1; cvt.u32.u64 %0, t; }"
        : "=r"(a) : "l"(p));
    return a;
}
__device__ __forceinline__ void ldsm4(uint32_t& r0, uint32_t& r1,
                                      uint32_t& r2, uint32_t& r3, uint32_t a) {
    asm volatile("ldmatrix.sync.aligned.m8n8.x4.shared.b16 {%0,%1,%2,%3}, [%4];"
                 : "=r"(r0), "=r"(r1), "=r"(r2), "=r"(r3) : "r"(a));
}
__device__ __forceinline__ void mma16816(float* c,
                                         uint32_t a0, uint32_t a1, uint32_t a2,
                                         uint32_t a3, uint32_t b0, uint32_t b1) {
    asm volatile(
        "mma.sync.aligned.m16n8k16.row.col.f32.bf16.bf16.f32 "
        "{%0,%1,%2,%3}, {%4,%5,%6,%7}, {%8,%9}, {%0,%1,%2,%3};"
        : "+f"(c[0]), "+f"(c[1]), "+f"(c[2]), "+f"(c[3])
        : "r"(a0), "r"(a1), "r"(a2), "r"(a3), "r"(b0), "r"(b1));
}
__device__ __forceinline__ uint32_t bpack(__nv_bfloat16 a, __nv_bfloat16 b) {
    __nv_bfloat162 t = __halves2bfloat162(a, b);
    return *(uint32_t*)&t;
}

// 4-head packed butterfly: lane l ends with the full 128-dim dot for head l&3.
__device__ __forceinline__ float reduce4(float v0, float v1, float v2, float v3,
                                         int lane)
{
    const bool b0 = lane & 1, b1 = lane & 2;
    float x = b0 ? v1 : v0;
    float y = b0 ? v0 : v1;
    x += __shfl_xor_sync(0xffffffffu, y, 1);
    float z = b0 ? v3 : v2;
    float u = b0 ? v2 : v3;
    z += __shfl_xor_sync(0xffffffffu, u, 1);
    float p = b1 ? z : x;
    float q = b1 ? x : z;
    p += __shfl_xor_sync(0xffffffffu, q, 2);
    p += __shfl_xor_sync(0xffffffffu, p, 4);
    p += __shfl_xor_sync(0xffffffffu, p, 8);
    p += __shfl_xor_sync(0xffffffffu, p, 16);
    return p;
}

// ---------------- GEMM staging ----------------------------------------------
struct WRegs {
    float4 v[4];
    float4 a;
};

__device__ __forceinline__ void ldg_chunk(WRegs& r,
    const float* __restrict__ A, int lda, int ka,
    const float* __restrict__ W, int kw)
{
    const int tid  = threadIdx.x;
    const int arow = tid >> 3, akq = (tid & 7) * 4;
    r.a = *(const float4*)(A + (size_t)arow * lda + ka + akq);
    const int brow = tid >> 1, bk = (tid & 1) * 16;
#pragma unroll
    for (int j = 0; j < 4; j++)
        r.v[j] = *(const float4*)(W + (size_t)brow * HIDDEN + kw + bk + j * 4);
}

__device__ __forceinline__ void sts_chunk(uint8_t* smem, int buf, const WRegs& r)
{
    const int tid  = threadIdx.x;
    const int arow = tid >> 3, akq = (tid & 7) * 4;
    uint8_t* A = smem + buf * A_BUF;
    {
        const __nv_bfloat16 h0 = __float2bfloat16(r.a.x);
        const __nv_bfloat16 h1 = __float2bfloat16(r.a.y);
        const __nv_bfloat16 h2 = __float2bfloat16(r.a.z);
        const __nv_bfloat16 h3 = __float2bfloat16(r.a.w);
        *(uint2*)(A + arow * 80 + akq * 2) =
            make_uint2(bpack(h0, h1), bpack(h2, h3));
        *(uint2*)(A + A_HL + arow * 80 + akq * 2) =
            make_uint2(bpack(__float2bfloat16(r.a.x - __bfloat162float(h0)),
                             __float2bfloat16(r.a.y - __bfloat162float(h1))),
                       bpack(__float2bfloat16(r.a.z - __bfloat162float(h2)),
                             __float2bfloat16(r.a.w - __bfloat162float(h3))));
    }

    const int brow = tid >> 1, bk = (tid & 1) * 16;
    uint8_t* Bh = smem + B_OFF + buf * B_BUF;
    uint8_t* Bl = Bh + B_HL;
    uint32_t h[8], l[8];
#pragma unroll
    for (int j = 0; j < 4; j++) {
        const float4 v = r.v[j];
        const __nv_bfloat16 h0 = __float2bfloat16(v.x);
        const __nv_bfloat16 h1 = __float2bfloat16(v.y);
        const __nv_bfloat16 h2 = __float2bfloat16(v.z);
        const __nv_bfloat16 h3 = __float2bfloat16(v.w);
        h[j * 2 + 0] = bpack(h0, h1);
        h[j * 2 + 1] = bpack(h2, h3);
        l[j * 2 + 0] = bpack(__float2bfloat16(v.x - __bfloat162float(h0)),
                             __float2bfloat16(v.y - __bfloat162float(h1)));
        l[j * 2 + 1] = bpack(__float2bfloat16(v.z - __bfloat162float(h2)),
                             __float2bfloat16(v.w - __bfloat162float(h3)));
    }
    *(uint4*)(Bh + brow * 80 + bk * 2)      = make_uint4(h[0], h[1], h[2], h[3]);
    *(uint4*)(Bh + brow * 80 + bk * 2 + 16) = make_uint4(h[4], h[5], h[6], h[7]);
    *(uint4*)(Bl + brow * 80 + bk * 2)      = make_uint4(l[0], l[1], l[2], l[3]);
    *(uint4*)(Bl + brow * 80 + bk * 2 + 16) = make_uint4(l[4], l[5], l[6], l[7]);
}

__device__ __forceinline__ void gemm_mma_body(
    const float* __restrict__ A, int lda, int a_k0,
    const float* __restrict__ W, int w_k0,
    float* __restrict__ outp, int nchunks)
{
    extern __shared__ uint8_t smem[];
    const uint32_t sb = smem_u32(smem);
    const int tid = threadIdx.x, warp = tid >> 5, lane = tid & 31;
    const int j = lane >> 3, r8 = lane & 7;

    float acc[2][2][4];
#pragma unroll
    for (int a = 0; a < 2; a++)
#pragma unroll
        for (int b = 0; b < 2; b++)
#pragma unroll
            for (int q = 0; q < 4; q++) acc[a][b][q] = 0.f;

    WRegs r;
    ldg_chunk(r, A, lda, a_k0, W, w_k0);
    sts_chunk(smem, 0, r);
    __syncthreads();

#pragma unroll 1
    for (int c = 0; c < nchunks; c++) {
        if (c + 1 < nchunks)
            ldg_chunk(r, A, lda, a_k0 + (c + 1) * KCH, W, w_k0 + (c + 1) * KCH);

        const uint32_t Ab = sb + (c & 1) * A_BUF;
        const uint32_t Bb = sb + B_OFF + (c & 1) * B_BUF;
#pragma unroll
        for (int ks = 0; ks < 2; ks++) {
            const uint32_t aaddr = Ab
                + (uint32_t)(((j & 1) * 8 + r8) * 80 + (ks * 2 + (j >> 1)) * 16);
            const uint32_t baddr = Bb
                + (uint32_t)((warp * 16 + (j >> 1) * 8 + r8) * 80
                             + (ks * 2 + (j & 1)) * 16);
            uint32_t f0, f1, f2, f3, g0, g1, g2, g3;
            uint32_t p0, p1, p2, p3, q0, q1, q2, q3;
            uint32_t bh0, bh1, bh2, bh3, bl0, bl1, bl2, bl3;
            ldsm4(f0, f1, f2, f3, aaddr);
            ldsm4(g0, g1, g2, g3, aaddr + 16 * 80);
            ldsm4(p0, p1, p2, p3, aaddr + A_HL);
            ldsm4(q0, q1, q2, q3, aaddr + A_HL + 16 * 80);
            ldsm4(bh0, bh1, bh2, bh3, baddr);
            ldsm4(bl0, bl1, bl2, bl3, baddr + B_HL);

            mma16816(acc[0][0], f0, f1, f2, f3, bh0, bh1);
            mma16816(acc[0][1], f0, f1, f2, f3, bh2, bh3);
            mma16816(acc[1][0], g0, g1, g2, g3, bh0, bh1);
            mma16816(acc[1][1], g0, g1, g2, g3, bh2, bh3);
            mma16816(acc[0][0], f0, f1, f2, f3, bl0, bl1);
            mma16816(acc[0][1], f0, f1, f2, f3, bl2, bl3);
            mma16816(acc[1][0], g0, g1, g2, g3, bl0, bl1);
            mma16816(acc[1][1], g0, g1, g2, g3, bl2, bl3);
            mma16816(acc[0][0], p0, p1, p2, p3, bh0, bh1);
            mma16816(acc[0][1], p0, p1, p2, p3, bh2, bh3);
            mma16816(acc[1][0], q0, q1, q2, q3, bh0, bh1);
            mma16816(acc[1][1], q0, q1, q2, q3, bh2, bh3);
        }
        if (c + 1 < nchunks) sts_chunk(smem, (c + 1) & 1, r);
        __syncthreads();
    }

#pragma unroll
    for (int mt = 0; mt < 2; mt++)
#pragma unroll
        for (int nh = 0; nh < 2; nh++) {
            const float* cc = acc[mt][nh];
            const int m0 = mt * 16 + (lane >> 2);
            const int n  = warp * 16 + nh * 8 + (lane & 3) * 2;
            *(float2*)(outp + (size_t)m0 * 128 + n)       = make_float2(cc[0], cc[1]);
            *(float2*)(outp + (size_t)(m0 + 8) * 128 + n) = make_float2(cc[2], cc[3]);
        }
}

// QKV: grid (24 tiles, KS) x 256. tiles 0-15 wq, 16-19 wk, 20-23 wv.
__global__ __launch_bounds__(256, 2) void gemm_qkv_mma(
    const float* __restrict__ x,
    const float* __restrict__ wq, const float* __restrict__ wk,
    const float* __restrict__ wv)
{
    const int tile = blockIdx.x, slice = blockIdx.y;
    const float* W;
    if (tile < 16)      W = wq + (size_t)tile * 128 * HIDDEN;
    else if (tile < 20) W = wk + (size_t)(tile - 16) * 128 * HIDDEN;
    else                W = wv + (size_t)(tile - 20) * 128 * HIDDEN;
    const int k0 = slice * (HIDDEN / KS);
    gemm_mma_body(x, HIDDEN, k0, W, k0,
                  g_part + (size_t)(tile * KS + slice) * 4096,
                  (HIDDEN / KS) / KCH);
}

// O-projection with fused flash combine. grid (16 tiles, KSO=16 slices) x 256.
// slice == head index; combine that head's partials into smem A (32x128),
// then a 4-chunk mainloop over W columns [slice*128, slice*128+128).
__global__ __launch_bounds__(256, 2) void gemm_o_mma(const float* __restrict__ wo)
{
    extern __shared__ uint8_t smem[];
    float* a_comb = (float*)(smem + SMEM_MMA);
    const int tile = blockIdx.x, slice = blockIdx.y;
    const int kv = slice >> 2, h = slice & 3;
    const int tid = threadIdx.x;

    for (int i = tid; i < 1024; i += 256) {
        const int b = i >> 5, d4 = (i & 31) * 4;
        const int pb = ((b * NKV + kv) * NSPLIT) * 4 + h;
        float den = 0.f;
#pragma unroll
        for (int c = 0; c < NSPLIT; c++) den += g_ps[pb + c * 4];
        float4 val = make_float4(0.f, 0.f, 0.f, 0.f);
#pragma unroll
        for (int c = 0; c < NSPLIT; c++) {
            const float4 v = *(const float4*)&g_pa[(size_t)(pb + c * 4) * HDIM + d4];
            val.x += v.x; val.y += v.y; val.z += v.z; val.w += v.w;
        }
        const float inv = 1.f / den;
        val.x *= inv; val.y *= inv; val.z *= inv; val.w *= inv;
        *(float4*)(a_comb + b * 128 + d4) = val;
    }
    __syncthreads();

    gemm_mma_body(a_comb, 128, 0, wo + (size_t)tile * 128 * HIDDEN, slice * 128,
                  g_part + (size_t)(tile * KSO + slice) * 4096,
                  128 / KCH);
}

// ---------------------------------------------------------------------------
// Attention partial with fused QKV-reduce + rmsnorm + RoPE prologue.
// Block (kv, b, split c) x 128 threads. Single-pass scoring, no max
// subtraction (Cauchy-Schwarz: ||q*QSCALE||=1 keeps exp fp32-safe).
// ---------------------------------------------------------------------------
__global__ __launch_bounds__(128) void attn_part(
    const float* __restrict__ k_cache, const float* __restrict__ v_cache,
    const float* __restrict__ position,
    const float* __restrict__ qnw, const float* __restrict__ knw)
{
    const int kv = blockIdx.x, b = blockIdx.y, c = blockIdx.z;
    const int tid = threadIdx.x;
    const int lane = tid & 31, w = tid >> 5;
    const int myh = lane & 3;
    const int pos = (int)position[0];
    const int S   = pos + 1;
    const int LEN = (S + NSPLIT - 1) / NSPLIT;
    const int lo  = c * LEN;
    const int hi  = min(S, lo + LEN);
    const int hic = min(hi, pos);
    const bool has_new = (pos >= lo) && (pos < hi);

    __shared__ float q_s[4][HDIM];
    __shared__ float kv_s[2][HDIM];          // [0]=k_new, [1]=v_new
    __shared__ float wred[4][4];
    __shared__ float wout[4][4][HDIM];

    // ---- fused reduce + rmsnorm + rope (6 warp tasks over 4 warps) ---------
    const int d4 = lane * 4;
    for (int task = w; task < 6; task += 4) {
        int tile, kind;                      // kind 0=q, 1=k, 2=v
        if (task < 4)       { tile = kv * 4 + task; kind = 0; }
        else if (task == 4) { tile = 16 + kv;       kind = 1; }
        else                { tile = 20 + kv;       kind = 2; }

        const float* base = g_part + (size_t)tile * KS * 4096
                            + (size_t)b * 128 + d4;
        float4 v4 = make_float4(0.f, 0.f, 0.f, 0.f);
#pragma unroll
        for (int s = 0; s < KS; s++) {
            const float4 p = *(const float4*)(base + (size_t)s * 4096);
            v4.x += p.x; v4.y += p.y; v4.z += p.z; v4.w += p.w;
        }
        if (kind == 2) {
            *(float4*)&kv_s[1][d4] = v4;
            continue;
        }
        float sq = v4.x * v4.x + v4.y * v4.y + v4.z * v4.z + v4.w * v4.w;
#pragma unroll
        for (int off = 16; off; off >>= 1)
            sq += __shfl_xor_sync(0xffffffffu, sq, off);
        const float norm = rsqrtf(sq * (1.f / 128.f) + EPSV);

        const float4 nw4 = (kind == 0) ? *(const float4*)(qnw + d4)
                                       : *(const float4*)(knw + d4);
        float nv[4] = { v4.x * norm * nw4.x, v4.y * norm * nw4.y,
                        v4.z * norm * nw4.z, v4.w * norm * nw4.w };
        float other[4];
#pragma unroll
        for (int i = 0; i < 4; i++)
            other[i] = __shfl_xor_sync(0xffffffffu, nv[i], 16);

        const float posf = position[0];
        const bool first = lane < 16;
        float outv[4];
#pragma unroll
        for (int i = 0; i < 4; i++) {
            const int jj = (d4 + i) & 63;
            const float fr = posf * exp2f((float)jj * (-19.93156856932417f / 64.f));
            float cc, ss;
            sincosf(fr, &ss, &cc);
            outv[i] = first ? (nv[i] * cc - other[i] * ss)
                            : (nv[i] * cc + other[i] * ss);
        }
        if (kind == 0) {
            q_s[task][d4 + 0] = outv[0] * QSCALE;
            q_s[task][d4 + 1] = outv[1] * QSCALE;
            q_s[task][d4 + 2] = outv[2] * QSCALE;
            q_s[task][d4 + 3] = outv[3] * QSCALE;
        } else {
            kv_s[0][d4 + 0] = outv[0];
            kv_s[0][d4 + 1] = outv[1];
            kv_s[0][d4 + 2] = outv[2];
            kv_s[0][d4 + 3] = outv[3];
        }
    }
    __syncthreads();

    float qr[4][4];
#pragma unroll
    for (int h = 0; h < 4; h++)
#pragma unroll
        for (int jj = 0; jj < 4; jj++) qr[h][jj] = q_s[h][lane * 4 + jj];

    const float* kbase = k_cache + (size_t)(b * NKV + kv) * MAXSEQ * HDIM + lane * 4;
    const float* vbase = v_cache + (size_t)(b * NKV + kv) * MAXSEQ * HDIM + lane * 4;

    float acc[4][4];
#pragma unroll
    for (int j = 0; j < 4; j++)
#pragma unroll
        for (int q = 0; q < 4; q++) acc[j][q] = 0.f;
    float lsum = 0.f;

    if (has_new && w == 0) {
        const float4 rk = *(const float4*)&kv_s[0][lane * 4];
        const float4 rv = *(const float4*)&kv_s[1][lane * 4];
        const float v0 = fmaf(rk.x, qr[0][0], fmaf(rk.y, qr[0][1],
                         fmaf(rk.z, qr[0][2], rk.w * qr[0][3])));
        const float v1 = fmaf(rk.x, qr[1][0], fmaf(rk.y, qr[1][1],
                         fmaf(rk.z, qr[1][2], rk.w * qr[1][3])));
        const float v2 = fmaf(rk.x, qr[2][0], fmaf(rk.y, qr[2][1],
                         fmaf(rk.z, qr[2][2], rk.w * qr[2][3])));
        const float v3 = fmaf(rk.x, qr[3][0], fmaf(rk.y, qr[3][1],
                         fmaf(rk.z, qr[3][2], rk.w * qr[3][3])));
        const float p = reduce4(v0, v1, v2, v3, lane);
        const float e = __expf(p);
        lsum += e;
        const float e1 = __shfl_xor_sync(0xffffffffu, e, 1);
        const float e2 = __shfl_xor_sync(0xffffffffu, e, 2);
        const float e3 = __shfl_xor_sync(0xffffffffu, e, 3);
        acc[0][0] = fmaf(e,  rv.x, acc[0][0]);
        acc[0][1] = fmaf(e,  rv.y, acc[0][1]);
        acc[0][2] = fmaf(e,  rv.z, acc[0][2]);
        acc[0][3] = fmaf(e,  rv.w, acc[0][3]);
        acc[1][0] = fmaf(e1, rv.x, acc[1][0]);
        acc[1][1] = fmaf(e1, rv.y, acc[1][1]);
        acc[1][2] = fmaf(e1, rv.z, acc[1][2]);
        acc[1][3] = fmaf(e1, rv.w, acc[1][3]);
        acc[2][0] = fmaf(e2, rv.x, acc[2][0]);
        acc[2][1] = fmaf(e2, rv.y, acc[2][1]);
        acc[2][2] = fmaf(e2, rv.z, acc[2][2]);
        acc[2][3] = fmaf(e2, rv.w, acc[2][3]);
        acc[3][0] = fmaf(e3, rv.x, acc[3][0]);
        acc[3][1] = fmaf(e3, rv.y, acc[3][1]);
        acc[3][2] = fmaf(e3, rv.z, acc[3][2]);
        acc[3][3] = fmaf(e3, rv.w, acc[3][3]);
    }

#define LOADG(dk, dv, s)                                                       \
    _Pragma("unroll")                                                          \
    for (int u_ = 0; u_ < 4; u_++) {                                           \
        const int ss_ = (s) + u_;                                              \
        if (ss_ < hic) {                                                       \
            dk[u_] = *(const float4*)(kbase + (size_t)ss_ * HDIM);             \
            dv[u_] = *(const float4*)(vbase + (size_t)ss_ * HDIM);             \
        }                                                                      \
    }

    int s0 = lo + w * 4;
    float4 rk[4], rv[4];
    if (s0 < hic) LOADG(rk, rv, s0);
#pragma unroll 1
    for (; s0 < hic; s0 += 16) {
        float4 nk[4], nv[4];
        const int s1 = s0 + 16;
        if (s1 < hic) LOADG(nk, nv, s1);
#pragma unroll
        for (int u = 0; u < 4; u++) {
            if (s0 + u < hic) {
                const float v0 = fmaf(rk[u].x, qr[0][0], fmaf(rk[u].y, qr[0][1],
                                 fmaf(rk[u].z, qr[0][2], rk[u].w * qr[0][3])));
                const float v1 = fmaf(rk[u].x, qr[1][0], fmaf(rk[u].y, qr[1][1],
                                 fmaf(rk[u].z, qr[1][2], rk[u].w * qr[1][3])));
                const float v2 = fmaf(rk[u].x, qr[2][0], fmaf(rk[u].y, qr[2][1],
                                 fmaf(rk[u].z, qr[2][2], rk[u].w * qr[2][3])));
                const float v3 = fmaf(rk[u].x, qr[3][0], fmaf(rk[u].y, qr[3][1],
                                 fmaf(rk[u].z, qr[3][2], rk[u].w * qr[3][3])));
                const float p = reduce4(v0, v1, v2, v3, lane);
                const float e = __expf(p);
                lsum += e;
                const float e1 = __shfl_xor_sync(0xffffffffu, e, 1);
                const float e2 = __shfl_xor_sync(0xffffffffu, e, 2);
                const float e3 = __shfl_xor_sync(0xffffffffu, e, 3);
                acc[0][0] = fmaf(e,  rv[u].x, acc[0][0]);
                acc[0][1] = fmaf(e,  rv[u].y, acc[0][1]);
                acc[0][2] = fmaf(e,  rv[u].z, acc[0][2]);
                acc[0][3] = fmaf(e,  rv[u].w, acc[0][3]);
                acc[1][0] = fmaf(e1, rv[u].x, acc[1][0]);
                acc[1][1] = fmaf(e1, rv[u].y, acc[1][1]);
                acc[1][2] = fmaf(e1, rv[u].z, acc[1][2]);
                acc[1][3] = fmaf(e1, rv[u].w, acc[1][3]);
                acc[2][0] = fmaf(e2, rv[u].x, acc[2][0]);
                acc[2][1] = fmaf(e2, rv[u].y, acc[2][1]);
                acc[2][2] = fmaf(e2, rv[u].z, acc[2][2]);
                acc[2][3] = fmaf(e2, rv[u].w, acc[2][3]);
                acc[3][0] = fmaf(e3, rv[u].x, acc[3][0]);
                acc[3][1] = fmaf(e3, rv[u].y, acc[3][1]);
                acc[3][2] = fmaf(e3, rv[u].z, acc[3][2]);
                acc[3][3] = fmaf(e3, rv[u].w, acc[3][3]);
            }
        }
#pragma unroll
        for (int u = 0; u < 4; u++) { rk[u] = nk[u]; rv[u] = nv[u]; }
    }
#undef LOADG

    if (lane < 4) wred[w][lane] = lsum;
#pragma unroll
    for (int j = 0; j < 4; j++) {
        float* wo_ = &wout[w][myh ^ j][lane * 4];
        wo_[0] = acc[j][0];
        wo_[1] = acc[j][1];
        wo_[2] = acc[j][2];
        wo_[3] = acc[j][3];
    }
    __syncthreads();

    if (tid < 4) {
        float v = wred[0][tid] + wred[1][tid] + wred[2][tid] + wred[3][tid];
        g_ps[((b * NKV + kv) * NSPLIT + c) * 4 + tid] = v;
    }

    for (int i = tid; i < 4 * HDIM; i += 128) {
        const int h = i >> 7, d = i & 127;
        const float v = wout[0][h][d] + wout[1][h][d]
                      + wout[2][h][d] + wout[3][h][d];
        g_pa[(((size_t)(b * NKV + kv) * NSPLIT + c) * 4 + h) * HDIM + d] = v;
    }
}

// Final reduce for O projection: sum KSO=16 slices. grid (16, 32) x 128.
__global__ __launch_bounds__(128) void reduce_out(float* __restrict__ out)
{
    const int tile = blockIdx.x, b = blockIdx.y, d = threadIdx.x;
    const size_t base = (size_t)tile * KSO * 4096 + (size_t)b * 128 + d;
    float v = 0.f;
#pragma unroll
    for (int s = 0; s < KSO; s++) v += g_part[base + (size_t)s * 4096];
    out[b * HIDDEN + tile * 128 + d] = v;
}

// ---------------------------------------------------------------------------
extern "C" void kernel_launch(void* const* d_in, const int* in_sizes, int n_in,
                              void* d_out, int out_size)
{
    const float* x        = (const float*)d_in[0];
    const float* position = (const float*)d_in[1];
    const float* k_cache  = (const float*)d_in[3];
    const float* v_cache  = (const float*)d_in[4];
    const float* wq       = (const float*)d_in[6];
    const float* wk       = (const float*)d_in[7];
    const float* wv       = (const float*)d_in[8];
    const float* wo       = (const float*)d_in[9];
    const float* qnw      = (const float*)d_in[10];
    const float* knw      = (const float*)d_in[11];
    float* out            = (float*)d_out;

    cudaFuncSetAttribute(gemm_qkv_mma, cudaFuncAttributeMaxDynamicSharedMemorySize, SMEM_MMA);
    cudaFuncSetAttribute(gemm_o_mma,   cudaFuncAttributeMaxDynamicSharedMemorySize, SMEM_O);

    gemm_qkv_mma<<<dim3(24, KS), 256, SMEM_MMA>>>(x, wq, wk, wv);
    attn_part<<<dim3(NKV, 32, NSPLIT), 128>>>(k_cache, v_cache, position, qnw, knw);
    gemm_o_mma<<<dim3(16, KSO), 256, SMEM_O>>>(wo);
    reduce_out<<<dim3(16, 32), 128>>>(out);
}